// round 4
// baseline (speedup 1.0000x reference)
#include <cuda_runtime.h>
#include <cstdint>
#include <cstddef>

#define NMAT   256
#define NFREQ  33
#define SLICE  (NMAT*NMAT)
#define NTUBE  (8*SLICE)

__device__ float g_Ar[8*NFREQ*SLICE];
__device__ float g_Ai[8*NFREQ*SLICE];
__device__ float g_Br[8*NFREQ*SLICE];
__device__ float g_Bi[8*NFREQ*SLICE];
__device__ float g_Cr[8*NFREQ*SLICE];
__device__ float g_Ci[8*NFREQ*SLICE];

// ---------------- compile-time trig ----------------
constexpr double PI_D = 3.14159265358979323846264338327950288;
constexpr double tay_sin(double x){ double t=x,s=x; for(int i=1;i<12;i++){ t*=-(x*x)/double((2*i)*(2*i+1)); s+=t; } return s; }
constexpr double tay_cos(double x){ double t=1,s=1; for(int i=1;i<12;i++){ t*=-(x*x)/double((2*i-1)*(2*i)); s+=t; } return s; }
constexpr double c_cos64(int n){ int m=((n%64)+64)%64; double sg=1; if(m>=32){m-=32;sg=-sg;} if(m>16){m=32-m;sg=-sg;} return sg*tay_cos(PI_D*m/32.0); }
constexpr double c_sin64(int n){ int m=((n%64)+64)%64; double sg=1; if(m>=32){m-=32;sg=-sg;} if(m>16){m=32-m;} return sg*tay_sin(PI_D*m/32.0); }

template<int N> struct CW   { static constexpr float v = (float)c_cos64(N); };
template<int N> struct NSW  { static constexpr float v = (float)(-c_sin64(N)); };
template<int N> struct ICW  { static constexpr float v = (float)(c_cos64(N)/32.0); };
template<int N> struct NISW { static constexpr float v = (float)(-c_sin64(N)/32.0); };

// ---------------- forward DFT chains ----------------
template<int K,int S> struct SumE {
    static __device__ __forceinline__ float f(const float (&e)[33]){
        return fmaf(e[S], CW<(K*S)&63>::v, SumE<K,S-1>::f(e)); }
};
template<int K> struct SumE<K,0> {
    static __device__ __forceinline__ float f(const float (&e)[33]){ return e[0]; }
};
template<int K,int S> struct SumO {
    static __device__ __forceinline__ float f(const float (&o)[33]){
        return fmaf(o[S], NSW<(K*S)&63>::v, SumO<K,S-1>::f(o)); }
};
template<int K> struct SumO<K,0> {
    static __device__ __forceinline__ float f(const float (&)[33]){ return 0.0f; }
};
template<int K> struct Fwd {
    static __device__ __forceinline__ void run(const float (&e)[33], const float (&o)[33],
                                               float* __restrict__ pr, float* __restrict__ pi){
        pr[(size_t)K<<16] = SumE<K,32>::f(e);
        pi[(size_t)K<<16] = SumO<K,31>::f(o);
        Fwd<K-1>::run(e, o, pr, pi);
    }
};
template<> struct Fwd<-1> {
    static __device__ __forceinline__ void run(const float (&)[33], const float (&)[33], float*, float*){}
};

// ---------------- inverse DFT chains ----------------
template<int T,int K> struct SumR {
    static __device__ __forceinline__ float f(const float (&R)[33]){
        return fmaf(R[K], ICW<(T*K)&63>::v, SumR<T,K-1>::f(R)); }
};
template<int T> struct SumR<T,0> {
    static __device__ __forceinline__ float f(const float (&)[33]){ return 0.0f; }
};
template<int T,int K> struct SumI {
    static __device__ __forceinline__ float f(const float (&I)[33]){
        return fmaf(I[K], NISW<(T*K)&63>::v, SumI<T,K-1>::f(I)); }
};
template<int T> struct SumI<T,0> {
    static __device__ __forceinline__ float f(const float (&)[33]){ return 0.0f; }
};
template<int T> struct Inv {
    static __device__ __forceinline__ void run(const float (&R)[33], const float (&I)[33],
                                               float* __restrict__ sw){
        float E = SumR<T,31>::f(R);
        E = fmaf(R[0], 0.015625f, E);
        E = fmaf(R[32], (T & 1) ? -0.015625f : 0.015625f, E);
        float O = SumI<T,31>::f(I);
        sw[T]    = E + O;
        sw[64-T] = E - O;
        Inv<T-1>::run(R, I, sw);
    }
};
template<> struct Inv<0> {
    static __device__ __forceinline__ void run(const float (&R)[33], const float (&)[33],
                                               float* __restrict__ sw){
        float E = SumR<0,31>::f(R);
        sw[0] = fmaf(R[0] + R[32], 0.015625f, E);
    }
};

// ---------------- Stage 1: forward rDFT ----------------
__global__ void __launch_bounds__(128) dft_fwd_kernel(const float* __restrict__ in, int which){
    __shared__ float sm[128*67];
    const int tid = threadIdx.x;
    const float4* in4 = (const float4*)(in + (size_t)blockIdx.x * 8192);
#pragma unroll
    for (int h = 0; h < 16; h++){
        int l4 = h*128 + tid;           // 0..2047
        float4 v = in4[l4];
        int tube = l4 >> 4;
        int s = (l4 & 15) * 4;
        float* p = &sm[tube*67 + s];
        p[0]=v.x; p[1]=v.y; p[2]=v.z; p[3]=v.w;
    }
    __syncthreads();

    const float* a = &sm[tid*67];
    float e[33], o[33];
    e[0] = a[0]; e[32] = a[32]; o[0] = 0.f; o[32] = 0.f;
#pragma unroll
    for (int s = 1; s < 32; s++){
        float x = a[s], y = a[64 - s];
        e[s] = x + y;
        o[s] = x - y;
    }
    const int T   = blockIdx.x*128 + tid;
    const size_t off = ((size_t)(T >> 16) * NFREQ << 16) + (T & 65535);
    float* pr = (which ? g_Br : g_Ar) + off;
    float* pi = (which ? g_Bi : g_Ai) + off;
    Fwd<32>::run(e, o, pr, pi);
}

// ---------------- Stage 2: complex GEMM (f32x2) ----------------
typedef unsigned long long ull;
__device__ __forceinline__ ull pack2(float x, float y){
    ull r; asm("mov.b64 %0, {%1,%2};" : "=l"(r) : "f"(x), "f"(y)); return r;
}
__device__ __forceinline__ float2 unpack2(ull v){
    float2 f; asm("mov.b64 {%0,%1}, %2;" : "=f"(f.x), "=f"(f.y) : "l"(v)); return f;
}
#define FMA2(d,a,b) asm("fma.rn.f32x2 %0, %1, %2, %0;" : "+l"(d) : "l"(a), "l"(b))

__global__ void __launch_bounds__(256, 1) zgemm_kernel(){
    __shared__ float As_re[16*132];
    __shared__ float As_im[16*132];
    __shared__ float Bs_re[16*128];
    __shared__ float Bs_im[16*128];

    const int slice = blockIdx.y;
    const float* __restrict__ Ar = g_Ar + ((size_t)slice << 16);
    const float* __restrict__ Ai = g_Ai + ((size_t)slice << 16);
    const float* __restrict__ Br = g_Br + ((size_t)slice << 16);
    const float* __restrict__ Bi = g_Bi + ((size_t)slice << 16);
    float* __restrict__ Cr = g_Cr + ((size_t)slice << 16);
    float* __restrict__ Ci = g_Ci + ((size_t)slice << 16);

    const int i0 = (blockIdx.x >> 1) * 128;
    const int n0 = (blockIdx.x & 1) * 128;
    const int t  = threadIdx.x;
    const int tx = t & 15, row0 = (t >> 4) * 8;
    const int tx2 = tx * 2;

    ull acr[8][4], aci[8][4];
#pragma unroll
    for (int r = 0; r < 8; r++)
#pragma unroll
        for (int p = 0; p < 4; p++){ acr[r][p] = 0ull; aci[r][p] = 0ull; }

    // staging registers
    float4 ra_re[2], ra_im[2], rb_re[2], rb_im[2];
    int a_row[2], a_c4[2], b_row[2], b_c4[2];
#pragma unroll
    for (int h = 0; h < 2; h++){
        int idx = t + h*256;
        a_row[h] = idx >> 2;  a_c4[h] = (idx & 3) * 4;
        b_row[h] = idx >> 5;  b_c4[h] = (idx & 31) * 4;
    }

    // preload first tile
#pragma unroll
    for (int h = 0; h < 2; h++){
        ra_re[h] = *(const float4*)(Ar + (i0 + a_row[h])*NMAT + a_c4[h]);
        ra_im[h] = *(const float4*)(Ai + (i0 + a_row[h])*NMAT + a_c4[h]);
        rb_re[h] = *(const float4*)(Br + (b_row[h])*NMAT + n0 + b_c4[h]);
        rb_im[h] = *(const float4*)(Bi + (b_row[h])*NMAT + n0 + b_c4[h]);
    }

    for (int jb = 0; jb < NMAT; jb += 16){
        // store staged tile to smem (A transposed)
#pragma unroll
        for (int h = 0; h < 2; h++){
            int row = a_row[h], c4 = a_c4[h];
            As_re[(c4+0)*132+row] = ra_re[h].x; As_re[(c4+1)*132+row] = ra_re[h].y;
            As_re[(c4+2)*132+row] = ra_re[h].z; As_re[(c4+3)*132+row] = ra_re[h].w;
            As_im[(c4+0)*132+row] = ra_im[h].x; As_im[(c4+1)*132+row] = ra_im[h].y;
            As_im[(c4+2)*132+row] = ra_im[h].z; As_im[(c4+3)*132+row] = ra_im[h].w;
            *(float4*)&Bs_re[b_row[h]*128 + b_c4[h]] = rb_re[h];
            *(float4*)&Bs_im[b_row[h]*128 + b_c4[h]] = rb_im[h];
        }
        __syncthreads();
        // prefetch next tile
        if (jb + 16 < NMAT){
#pragma unroll
            for (int h = 0; h < 2; h++){
                ra_re[h] = *(const float4*)(Ar + (i0 + a_row[h])*NMAT + jb + 16 + a_c4[h]);
                ra_im[h] = *(const float4*)(Ai + (i0 + a_row[h])*NMAT + jb + 16 + a_c4[h]);
                rb_re[h] = *(const float4*)(Br + (jb + 16 + b_row[h])*NMAT + n0 + b_c4[h]);
                rb_im[h] = *(const float4*)(Bi + (jb + 16 + b_row[h])*NMAT + n0 + b_c4[h]);
            }
        }
        // compute
#pragma unroll 2
        for (int k = 0; k < 16; k++){
            float4 arv0 = *(const float4*)&As_re[k*132 + row0];
            float4 arv1 = *(const float4*)&As_re[k*132 + row0 + 4];
            float4 aiv0 = *(const float4*)&As_im[k*132 + row0];
            float4 aiv1 = *(const float4*)&As_im[k*132 + row0 + 4];
            float ar[8] = {arv0.x,arv0.y,arv0.z,arv0.w,arv1.x,arv1.y,arv1.z,arv1.w};
            float ai[8] = {aiv0.x,aiv0.y,aiv0.z,aiv0.w,aiv1.x,aiv1.y,aiv1.z,aiv1.w};
            ull br2[4], bi2[4], nbi2[4];
#pragma unroll
            for (int p = 0; p < 4; p++){
                br2[p]  = *(const ull*)&Bs_re[k*128 + tx2 + p*32];
                bi2[p]  = *(const ull*)&Bs_im[k*128 + tx2 + p*32];
                nbi2[p] = bi2[p] ^ 0x8000000080000000ULL;
            }
#pragma unroll
            for (int r = 0; r < 8; r++){
                ull ar2 = pack2(ar[r], ar[r]);
                ull ai2 = pack2(ai[r], ai[r]);
#pragma unroll
                for (int p = 0; p < 4; p++){
                    FMA2(acr[r][p], ar2, br2[p]);
                    FMA2(acr[r][p], ai2, nbi2[p]);
                    FMA2(aci[r][p], ar2, bi2[p]);
                    FMA2(aci[r][p], ai2, br2[p]);
                }
            }
        }
        __syncthreads();
    }

    // epilogue
#pragma unroll
    for (int r = 0; r < 8; r++){
        float* cr_row = Cr + (size_t)(i0 + row0 + r)*NMAT + n0;
        float* ci_row = Ci + (size_t)(i0 + row0 + r)*NMAT + n0;
#pragma unroll
        for (int p = 0; p < 4; p++){
            *(float2*)(cr_row + tx2 + p*32) = unpack2(acr[r][p]);
            *(float2*)(ci_row + tx2 + p*32) = unpack2(aci[r][p]);
        }
    }
}

// ---------------- Stage 3: inverse rDFT ----------------
__global__ void __launch_bounds__(128) idft_kernel(float* __restrict__ out){
    const int T = blockIdx.x*128 + threadIdx.x;
    const int b = T >> 16;
    const int idx = T & 65535;
    const float* __restrict__ cr = g_Cr + ((size_t)b*NFREQ << 16) + idx;
    const float* __restrict__ ci = g_Ci + ((size_t)b*NFREQ << 16) + idx;
    float R[33], I[33];
#pragma unroll
    for (int k = 0; k < 33; k++){
        R[k] = cr[(size_t)k << 16];
        I[k] = ci[(size_t)k << 16];
    }
    float* sw = out + (size_t)T * 64;
    Inv<32>::run(R, I, sw);
}

// ---------------- launch ----------------
extern "C" void kernel_launch(void* const* d_in, const int* in_sizes, int n_in,
                              void* d_out, int out_size){
    const float* A = (const float*)d_in[0];
    const float* B = (const float*)d_in[1];
    float* out = (float*)d_out;

    dft_fwd_kernel<<<NTUBE/128, 128>>>(A, 0);
    dft_fwd_kernel<<<NTUBE/128, 128>>>(B, 1);
    zgemm_kernel<<<dim3(4, 8*NFREQ), 256>>>();
    idft_kernel<<<NTUBE/128, 128>>>(out);
}

// round 6
// speedup vs baseline: 1.1108x; 1.1108x over previous
#include <cuda_runtime.h>
#include <cstdint>
#include <cstddef>

#define NMAT   256
#define NFREQ  33
#define SLICE  (NMAT*NMAT)
#define NTUBE  (8*SLICE)

__device__ float g_Ar[8*NFREQ*SLICE];   // [slice][i*256+j]
__device__ float g_Ai[8*NFREQ*SLICE];
__device__ float g_Br[8*NFREQ*SLICE];   // [slice][n*256+j]  (n-major, j = K dim)
__device__ float g_Bi[8*NFREQ*SLICE];
__device__ float g_Cr[8*NFREQ*SLICE];   // [slice][i*256+n]
__device__ float g_Ci[8*NFREQ*SLICE];

// ---------------- compile-time trig ----------------
constexpr double PI_D = 3.14159265358979323846264338327950288;
constexpr double tay_sin(double x){ double t=x,s=x; for(int i=1;i<12;i++){ t*=-(x*x)/double((2*i)*(2*i+1)); s+=t; } return s; }
constexpr double tay_cos(double x){ double t=1,s=1; for(int i=1;i<12;i++){ t*=-(x*x)/double((2*i-1)*(2*i)); s+=t; } return s; }
constexpr double c_cos64(int n){ int m=((n%64)+64)%64; double sg=1; if(m>=32){m-=32;sg=-sg;} if(m>16){m=32-m;sg=-sg;} return sg*tay_cos(PI_D*m/32.0); }
constexpr double c_sin64(int n){ int m=((n%64)+64)%64; double sg=1; if(m>=32){m-=32;sg=-sg;} if(m>16){m=32-m;} return sg*tay_sin(PI_D*m/32.0); }

template<int N> struct CW   { static constexpr float v = (float)c_cos64(N); };
template<int N> struct NSW  { static constexpr float v = (float)(-c_sin64(N)); };
template<int N> struct ICW  { static constexpr float v = (float)(c_cos64(N)/32.0); };
template<int N> struct NISW { static constexpr float v = (float)(-c_sin64(N)/32.0); };

// ---------------- forward DFT chains ----------------
template<int K,int S> struct SumE {
    static __device__ __forceinline__ float f(const float (&e)[33]){
        return fmaf(e[S], CW<(K*S)&63>::v, SumE<K,S-1>::f(e)); }
};
template<int K> struct SumE<K,0> {
    static __device__ __forceinline__ float f(const float (&e)[33]){ return e[0]; }
};
template<int K,int S> struct SumO {
    static __device__ __forceinline__ float f(const float (&o)[33]){
        return fmaf(o[S], NSW<(K*S)&63>::v, SumO<K,S-1>::f(o)); }
};
template<int K> struct SumO<K,0> {
    static __device__ __forceinline__ float f(const float (&)[33]){ return 0.0f; }
};
template<int K> struct Fwd {
    static __device__ __forceinline__ void run(const float (&e)[33], const float (&o)[33],
                                               float* __restrict__ pr, float* __restrict__ pi){
        pr[(size_t)K<<16] = SumE<K,32>::f(e);
        pi[(size_t)K<<16] = SumO<K,31>::f(o);
        Fwd<K-1>::run(e, o, pr, pi);
    }
};
template<> struct Fwd<-1> {
    static __device__ __forceinline__ void run(const float (&)[33], const float (&)[33], float*, float*){}
};

// ---------------- inverse DFT chains ----------------
template<int T,int K> struct SumR {
    static __device__ __forceinline__ float f(const float (&R)[33]){
        return fmaf(R[K], ICW<(T*K)&63>::v, SumR<T,K-1>::f(R)); }
};
template<int T> struct SumR<T,0> {
    static __device__ __forceinline__ float f(const float (&)[33]){ return 0.0f; }
};
template<int T,int K> struct SumI {
    static __device__ __forceinline__ float f(const float (&I)[33]){
        return fmaf(I[K], NISW<(T*K)&63>::v, SumI<T,K-1>::f(I)); }
};
template<int T> struct SumI<T,0> {
    static __device__ __forceinline__ float f(const float (&)[33]){ return 0.0f; }
};
template<int T> struct Inv {
    static __device__ __forceinline__ void run(const float (&R)[33], const float (&I)[33],
                                               float* __restrict__ sw){
        float E = SumR<T,31>::f(R);
        E = fmaf(R[0], 0.015625f, E);
        E = fmaf(R[32], (T & 1) ? -0.015625f : 0.015625f, E);
        float O = SumI<T,31>::f(I);
        sw[T]    = E + O;
        sw[64-T] = E - O;
        Inv<T-1>::run(R, I, sw);
    }
};
template<> struct Inv<0> {
    static __device__ __forceinline__ void run(const float (&R)[33], const float (&)[33],
                                               float* __restrict__ sw){
        float E = SumR<0,31>::f(R);
        sw[0] = fmaf(R[0] + R[32], 0.015625f, E);
    }
};

// ---------------- Stage 1a: forward rDFT for A ----------------
__global__ void __launch_bounds__(128) dft_fwd_A(const float* __restrict__ in){
    __shared__ float sm[128*67];
    const int tid = threadIdx.x;
    const float4* in4 = (const float4*)(in + (size_t)blockIdx.x * 8192);
#pragma unroll
    for (int h = 0; h < 16; h++){
        int l4 = h*128 + tid;
        float4 v = in4[l4];
        int tube = l4 >> 4;
        int s = (l4 & 15) * 4;
        float* p = &sm[tube*67 + s];
        p[0]=v.x; p[1]=v.y; p[2]=v.z; p[3]=v.w;
    }
    __syncthreads();

    const float* a = &sm[tid*67];
    float e[33], o[33];
    e[0] = a[0]; e[32] = a[32]; o[0] = 0.f; o[32] = 0.f;
#pragma unroll
    for (int s = 1; s < 32; s++){
        float x = a[s], y = a[64 - s];
        e[s] = x + y; o[s] = x - y;
    }
    const int T   = blockIdx.x*128 + tid;
    const size_t off = ((size_t)(T >> 16) * NFREQ << 16) + (T & 65535);
    Fwd<32>::run(e, o, g_Ar + off, g_Ai + off);
}

// ---------------- Stage 1b: forward rDFT for B, transposed write [k][n][j] ----------------
__global__ void __launch_bounds__(128) dft_fwd_B(const float* __restrict__ in){
    __shared__ float sm[128*67];
    const int tid = threadIdx.x;
    const int blk = blockIdx.x;
    const int b   = blk >> 9;
    const int rem = blk & 511;
    const int j0  = (rem >> 6) << 5;   // 0..224 step 32
    const int n0  = (rem & 63) << 2;   // 0..252 step 4
    const float4* base4 = (const float4*)(in + (size_t)b * SLICE * 64);
#pragma unroll
    for (int h = 0; h < 16; h++){
        int l4 = h*128 + tid;
        int jl  = l4 >> 6;
        int r64 = l4 & 63;
        float4 v = base4[(size_t)((j0 + jl)*NMAT + n0)*16 + r64];
        int tube = (r64 >> 4)*32 + jl;
        int s = (r64 & 15) * 4;
        float* p = &sm[tube*67 + s];
        p[0]=v.x; p[1]=v.y; p[2]=v.z; p[3]=v.w;
    }
    __syncthreads();

    const float* a = &sm[tid*67];
    float e[33], o[33];
    e[0] = a[0]; e[32] = a[32]; o[0] = 0.f; o[32] = 0.f;
#pragma unroll
    for (int s = 1; s < 32; s++){
        float x = a[s], y = a[64 - s];
        e[s] = x + y; o[s] = x - y;
    }
    const int jg = j0 + (tid & 31);
    const int ng = n0 + (tid >> 5);
    const size_t off = ((size_t)b * NFREQ << 16) + ng*NMAT + jg;
    Fwd<32>::run(e, o, g_Br + off, g_Bi + off);
}

// ---------------- Stage 2: Gauss 3-mult complex GEMM (f32x2 SIMT) ----------------
typedef unsigned long long ull;
__device__ __forceinline__ ull pack2(float x, float y){
    ull r; asm("mov.b64 %0, {%1,%2};" : "=l"(r) : "f"(x), "f"(y)); return r;
}
__device__ __forceinline__ float2 unpack2(ull v){
    float2 f; asm("mov.b64 {%0,%1}, %2;" : "=f"(f.x), "=f"(f.y) : "l"(v)); return f;
}
#define FMA2(d,a,b) asm("fma.rn.f32x2 %0, %1, %2, %0;" : "+l"(d) : "l"(a), "l"(b))
#define ADD2(d,a,b) asm("add.rn.f32x2 %0, %1, %2;" : "=l"(d) : "l"(a), "l"(b))

// tile: 128 rows (i) x 64 cols (n); 256 threads; thread = 8 rows x 4 cols (2 pairs)
template<bool REALK>
__global__ void __launch_bounds__(256, 1) zgemm_g(){
    __shared__ float As_re[16*132];
    __shared__ float As_im[16*132];
    __shared__ float Bs_re[16*68];
    __shared__ float Bs_im[16*68];
    __shared__ float Bs_s [16*68];

    const int by = blockIdx.y;
    const int slice = REALK ? ((by >> 1)*33 + ((by & 1) << 5))
                            : ((by / 31)*33 + 1 + (by % 31));
    const float* __restrict__ Ar = g_Ar + ((size_t)slice << 16);
    const float* __restrict__ Ai = g_Ai + ((size_t)slice << 16);
    const float* __restrict__ Br = g_Br + ((size_t)slice << 16);
    const float* __restrict__ Bi = g_Bi + ((size_t)slice << 16);
    float* __restrict__ Cr = g_Cr + ((size_t)slice << 16);
    float* __restrict__ Ci = g_Ci + ((size_t)slice << 16);

    const int i0 = (blockIdx.x >> 2) * 128;
    const int n0 = (blockIdx.x & 3) * 64;
    const int t  = threadIdx.x;
    const int ty = t >> 4, tx = t & 15;
    const int r0 = ty * 8;

    ull t1[8][2], t2[8][2], t3[8][2];
#pragma unroll
    for (int r = 0; r < 8; r++)
#pragma unroll
        for (int p = 0; p < 2; p++){ t1[r][p]=0ull; t2[r][p]=0ull; t3[r][p]=0ull; }

    // load index mapping
    int a_row[2], a_k4[2];
#pragma unroll
    for (int h = 0; h < 2; h++){
        int idx = t + h*256;
        a_row[h] = idx >> 2;  a_k4[h] = (idx & 3) * 4;
    }
    const int b_n = t >> 2, b_k4 = (t & 3) * 4;

    float4 va_r[2], va_i[2], vb_r, vb_i;
#pragma unroll
    for (int h = 0; h < 2; h++){
        va_r[h] = *(const float4*)(Ar + (size_t)(i0 + a_row[h])*NMAT + a_k4[h]);
        if (!REALK) va_i[h] = *(const float4*)(Ai + (size_t)(i0 + a_row[h])*NMAT + a_k4[h]);
    }
    vb_r = *(const float4*)(Br + (size_t)(n0 + b_n)*NMAT + b_k4);
    if (!REALK) vb_i = *(const float4*)(Bi + (size_t)(n0 + b_n)*NMAT + b_k4);

    for (int c = 0; c < 16; c++){
        // ---- STS (A transposed [k][row], B transposed [k][n] + sum plane) ----
#pragma unroll
        for (int h = 0; h < 2; h++){
            const float* vr = &va_r[h].x;
            const float* vi = &va_i[h].x;
#pragma unroll
            for (int s = 0; s < 4; s++){
                As_re[(a_k4[h]+s)*132 + a_row[h]] = vr[s];
                if (!REALK) As_im[(a_k4[h]+s)*132 + a_row[h]] = vi[s];
            }
        }
        {
            const float* vr = &vb_r.x;
            const float* vi = &vb_i.x;
#pragma unroll
            for (int s = 0; s < 4; s++){
                Bs_re[(b_k4+s)*68 + b_n] = vr[s];
                if (!REALK){
                    Bs_im[(b_k4+s)*68 + b_n] = vi[s];
                    Bs_s [(b_k4+s)*68 + b_n] = vr[s] + vi[s];
                }
            }
        }
        __syncthreads();
        // ---- prefetch next chunk ----
        if (c < 15){
            int kb = (c + 1) * 16;
#pragma unroll
            for (int h = 0; h < 2; h++){
                va_r[h] = *(const float4*)(Ar + (size_t)(i0 + a_row[h])*NMAT + kb + a_k4[h]);
                if (!REALK) va_i[h] = *(const float4*)(Ai + (size_t)(i0 + a_row[h])*NMAT + kb + a_k4[h]);
            }
            vb_r = *(const float4*)(Br + (size_t)(n0 + b_n)*NMAT + kb + b_k4);
            if (!REALK) vb_i = *(const float4*)(Bi + (size_t)(n0 + b_n)*NMAT + kb + b_k4);
        }
        // ---- compute 16 k-steps ----
#pragma unroll 4
        for (int k = 0; k < 16; k++){
            ulonglong2 bru = *(const ulonglong2*)&Bs_re[k*68 + tx*4];
            ull br2[2] = {bru.x, bru.y};
            ull bi2[2], bs2[2];
            if (!REALK){
                ulonglong2 biu = *(const ulonglong2*)&Bs_im[k*68 + tx*4];
                ulonglong2 bsu = *(const ulonglong2*)&Bs_s [k*68 + tx*4];
                bi2[0]=biu.x; bi2[1]=biu.y; bs2[0]=bsu.x; bs2[1]=bsu.y;
            }
            float4 a0 = *(const float4*)&As_re[k*132 + r0];
            float4 a1 = *(const float4*)&As_re[k*132 + r0 + 4];
            float arf[8] = {a0.x,a0.y,a0.z,a0.w,a1.x,a1.y,a1.z,a1.w};
            float aif[8];
            if (!REALK){
                float4 b0 = *(const float4*)&As_im[k*132 + r0];
                float4 b1 = *(const float4*)&As_im[k*132 + r0 + 4];
                aif[0]=b0.x; aif[1]=b0.y; aif[2]=b0.z; aif[3]=b0.w;
                aif[4]=b1.x; aif[5]=b1.y; aif[6]=b1.z; aif[7]=b1.w;
            }
#pragma unroll
            for (int r = 0; r < 8; r++){
                ull ar2 = pack2(arf[r], arf[r]);
                FMA2(t1[r][0], ar2, br2[0]);
                FMA2(t1[r][1], ar2, br2[1]);
                if (!REALK){
                    ull ai2 = pack2(aif[r], aif[r]);
                    ull as2; ADD2(as2, ar2, ai2);
                    FMA2(t2[r][0], ai2, bi2[0]);
                    FMA2(t2[r][1], ai2, bi2[1]);
                    FMA2(t3[r][0], as2, bs2[0]);
                    FMA2(t3[r][1], as2, bs2[1]);
                }
            }
        }
        __syncthreads();
    }

    // ---- epilogue: Cr = T1 - T2 ; Ci = T3 - T1 - T2 ----
#pragma unroll
    for (int r = 0; r < 8; r++){
        float* crp = Cr + (size_t)(i0 + r0 + r)*NMAT + n0 + tx*4;
        float* cip = Ci + (size_t)(i0 + r0 + r)*NMAT + n0 + tx*4;
        float2 x0 = unpack2(t1[r][0]), x1 = unpack2(t1[r][1]);
        if (REALK){
            float4 vr; vr.x=x0.x; vr.y=x0.y; vr.z=x1.x; vr.w=x1.y;
            *(float4*)crp = vr;
            *(float4*)cip = make_float4(0.f,0.f,0.f,0.f);
        } else {
            float2 y0 = unpack2(t2[r][0]), y1 = unpack2(t2[r][1]);
            float2 z0 = unpack2(t3[r][0]), z1 = unpack2(t3[r][1]);
            float4 vr, vi;
            vr.x = x0.x - y0.x;  vr.y = x0.y - y0.y;
            vr.z = x1.x - y1.x;  vr.w = x1.y - y1.y;
            vi.x = z0.x - x0.x - y0.x;  vi.y = z0.y - x0.y - y0.y;
            vi.z = z1.x - x1.x - y1.x;  vi.w = z1.y - x1.y - y1.y;
            *(float4*)crp = vr;
            *(float4*)cip = vi;
        }
    }
}

// ---------------- Stage 3: inverse rDFT (smem-staged coalesced stores) ----------------
__global__ void __launch_bounds__(128) idft_kernel(float* __restrict__ out){
    __shared__ float sm[128*67];
    const int tid = threadIdx.x;
    const int T = blockIdx.x*128 + tid;
    const int b = T >> 16;
    const int idx = T & 65535;
    const float* __restrict__ cr = g_Cr + ((size_t)b*NFREQ << 16) + idx;
    const float* __restrict__ ci = g_Ci + ((size_t)b*NFREQ << 16) + idx;
    float R[33], I[33];
#pragma unroll
    for (int k = 0; k < 33; k++){
        R[k] = cr[(size_t)k << 16];
        I[k] = ci[(size_t)k << 16];
    }
    Inv<32>::run(R, I, &sm[tid*67]);
    __syncthreads();
    float4* out4 = (float4*)(out + (size_t)blockIdx.x * 8192);
#pragma unroll
    for (int h = 0; h < 16; h++){
        int l4 = h*128 + tid;
        int tube = l4 >> 4;
        int s4 = l4 & 15;
        const float* p = &sm[tube*67 + s4*4];
        float4 v; v.x = p[0]; v.y = p[1]; v.z = p[2]; v.w = p[3];
        out4[l4] = v;
    }
}

// ---------------- launch ----------------
extern "C" void kernel_launch(void* const* d_in, const int* in_sizes, int n_in,
                              void* d_out, int out_size){
    const float* A = (const float*)d_in[0];
    const float* B = (const float*)d_in[1];
    float* out = (float*)d_out;

    dft_fwd_A<<<NTUBE/128, 128>>>(A);
    dft_fwd_B<<<NTUBE/128, 128>>>(B);
    zgemm_g<false><<<dim3(8, 248), 256>>>();
    zgemm_g<true ><<<dim3(8, 16),  256>>>();
    idft_kernel<<<NTUBE/128, 128>>>(out);
}

// round 7
// speedup vs baseline: 2.1946x; 1.9757x over previous
#include <cuda_runtime.h>
#include <cstdint>
#include <cstddef>

#define NMAT   256
#define NFREQ  33
#define SLICE  (NMAT*NMAT)
#define NTUBE  (8*SLICE)

__device__ float g_Ar[8*NFREQ*SLICE];   // [slice][i*256+j]  (tf32-rounded)
__device__ float g_Ai[8*NFREQ*SLICE];
__device__ float g_Br[8*NFREQ*SLICE];   // [slice][n*256+j]  (tf32-rounded)
__device__ float g_Bi[8*NFREQ*SLICE];
__device__ float g_Cr[8*NFREQ*SLICE];   // [slice][i*256+n]  (fp32)
__device__ float g_Ci[8*NFREQ*SLICE];

// ---------------- compile-time trig ----------------
constexpr double PI_D = 3.14159265358979323846264338327950288;
constexpr double tay_sin(double x){ double t=x,s=x; for(int i=1;i<12;i++){ t*=-(x*x)/double((2*i)*(2*i+1)); s+=t; } return s; }
constexpr double tay_cos(double x){ double t=1,s=1; for(int i=1;i<12;i++){ t*=-(x*x)/double((2*i-1)*(2*i)); s+=t; } return s; }
constexpr double c_cos64(int n){ int m=((n%64)+64)%64; double sg=1; if(m>=32){m-=32;sg=-sg;} if(m>16){m=32-m;sg=-sg;} return sg*tay_cos(PI_D*m/32.0); }
constexpr double c_sin64(int n){ int m=((n%64)+64)%64; double sg=1; if(m>=32){m-=32;sg=-sg;} if(m>16){m=32-m;} return sg*tay_sin(PI_D*m/32.0); }

template<int N> struct CW   { static constexpr float v = (float)c_cos64(N); };
template<int N> struct NSW  { static constexpr float v = (float)(-c_sin64(N)); };
template<int N> struct ICW  { static constexpr float v = (float)(c_cos64(N)/32.0); };
template<int N> struct NISW { static constexpr float v = (float)(-c_sin64(N)/32.0); };

__device__ __forceinline__ float tf32f(float x){
    uint32_t u; asm("cvt.rna.tf32.f32 %0, %1;" : "=r"(u) : "f"(x));
    return __uint_as_float(u);
}
__device__ __forceinline__ uint32_t tf32b(float x){
    uint32_t u; asm("cvt.rna.tf32.f32 %0, %1;" : "=r"(u) : "f"(x));
    return u;
}

// ---------------- forward DFT chains ----------------
template<int K,int S> struct SumE {
    static __device__ __forceinline__ float f(const float (&e)[33]){
        return fmaf(e[S], CW<(K*S)&63>::v, SumE<K,S-1>::f(e)); }
};
template<int K> struct SumE<K,0> {
    static __device__ __forceinline__ float f(const float (&e)[33]){ return e[0]; }
};
template<int K,int S> struct SumO {
    static __device__ __forceinline__ float f(const float (&o)[33]){
        return fmaf(o[S], NSW<(K*S)&63>::v, SumO<K,S-1>::f(o)); }
};
template<int K> struct SumO<K,0> {
    static __device__ __forceinline__ float f(const float (&)[33]){ return 0.0f; }
};
template<int K> struct Fwd {
    static __device__ __forceinline__ void run(const float (&e)[33], const float (&o)[33],
                                               float* __restrict__ pr, float* __restrict__ pi){
        pr[(size_t)K<<16] = tf32f(SumE<K,32>::f(e));
        pi[(size_t)K<<16] = tf32f(SumO<K,31>::f(o));
        Fwd<K-1>::run(e, o, pr, pi);
    }
};
template<> struct Fwd<-1> {
    static __device__ __forceinline__ void run(const float (&)[33], const float (&)[33], float*, float*){}
};

// ---------------- inverse DFT chains ----------------
template<int T,int K> struct SumR {
    static __device__ __forceinline__ float f(const float (&R)[33]){
        return fmaf(R[K], ICW<(T*K)&63>::v, SumR<T,K-1>::f(R)); }
};
template<int T> struct SumR<T,0> {
    static __device__ __forceinline__ float f(const float (&)[33]){ return 0.0f; }
};
template<int T,int K> struct SumI {
    static __device__ __forceinline__ float f(const float (&I)[33]){
        return fmaf(I[K], NISW<(T*K)&63>::v, SumI<T,K-1>::f(I)); }
};
template<int T> struct SumI<T,0> {
    static __device__ __forceinline__ float f(const float (&)[33]){ return 0.0f; }
};
template<int T> struct Inv {
    static __device__ __forceinline__ void run(const float (&R)[33], const float (&I)[33],
                                               float* __restrict__ sw){
        float E = SumR<T,31>::f(R);
        E = fmaf(R[0], 0.015625f, E);
        E = fmaf(R[32], (T & 1) ? -0.015625f : 0.015625f, E);
        float O = SumI<T,31>::f(I);
        sw[T]    = E + O;
        sw[64-T] = E - O;
        Inv<T-1>::run(R, I, sw);
    }
};
template<> struct Inv<0> {
    static __device__ __forceinline__ void run(const float (&R)[33], const float (&)[33],
                                               float* __restrict__ sw){
        float E = SumR<0,31>::f(R);
        sw[0] = fmaf(R[0] + R[32], 0.015625f, E);
    }
};

// ---------------- Stage 1a: forward rDFT for A ----------------
__global__ void __launch_bounds__(128) dft_fwd_A(const float* __restrict__ in){
    __shared__ float sm[128*67];
    const int tid = threadIdx.x;
    const float4* in4 = (const float4*)(in + (size_t)blockIdx.x * 8192);
#pragma unroll
    for (int h = 0; h < 16; h++){
        int l4 = h*128 + tid;
        float4 v = in4[l4];
        int tube = l4 >> 4;
        int s = (l4 & 15) * 4;
        float* p = &sm[tube*67 + s];
        p[0]=v.x; p[1]=v.y; p[2]=v.z; p[3]=v.w;
    }
    __syncthreads();

    const float* a = &sm[tid*67];
    float e[33], o[33];
    e[0] = a[0]; e[32] = a[32]; o[0] = 0.f; o[32] = 0.f;
#pragma unroll
    for (int s = 1; s < 32; s++){
        float x = a[s], y = a[64 - s];
        e[s] = x + y; o[s] = x - y;
    }
    const int T   = blockIdx.x*128 + tid;
    const size_t off = ((size_t)(T >> 16) * NFREQ << 16) + (T & 65535);
    Fwd<32>::run(e, o, g_Ar + off, g_Ai + off);
}

// ---------------- Stage 1b: forward rDFT for B, transposed write [k][n][j] ----------------
__global__ void __launch_bounds__(128) dft_fwd_B(const float* __restrict__ in){
    __shared__ float sm[128*67];
    const int tid = threadIdx.x;
    const int blk = blockIdx.x;
    const int b   = blk >> 9;
    const int rem = blk & 511;
    const int j0  = (rem >> 6) << 5;
    const int n0  = (rem & 63) << 2;
    const float4* base4 = (const float4*)(in + (size_t)b * SLICE * 64);
#pragma unroll
    for (int h = 0; h < 16; h++){
        int l4 = h*128 + tid;
        int jl  = l4 >> 6;
        int r64 = l4 & 63;
        float4 v = base4[(size_t)((j0 + jl)*NMAT + n0)*16 + r64];
        int tube = (r64 >> 4)*32 + jl;
        int s = (r64 & 15) * 4;
        float* p = &sm[tube*67 + s];
        p[0]=v.x; p[1]=v.y; p[2]=v.z; p[3]=v.w;
    }
    __syncthreads();

    const float* a = &sm[tid*67];
    float e[33], o[33];
    e[0] = a[0]; e[32] = a[32]; o[0] = 0.f; o[32] = 0.f;
#pragma unroll
    for (int s = 1; s < 32; s++){
        float x = a[s], y = a[64 - s];
        e[s] = x + y; o[s] = x - y;
    }
    const int jg = j0 + (tid & 31);
    const int ng = n0 + (tid >> 5);
    const size_t off = ((size_t)b * NFREQ << 16) + ng*NMAT + jg;
    Fwd<32>::run(e, o, g_Br + off, g_Bi + off);
}

// ---------------- Stage 2: mma.sync tf32 Gauss complex GEMM ----------------
__device__ __forceinline__ uint32_t s2u(const void* p){
    uint32_t a;
    asm("{ .reg .u64 t; cvta.to.shared.u64 t, %1; cvt.u32.u64 %0, t; }" : "=r"(a) : "l"(p));
    return a;
}
#define CP16(dst, src) asm volatile("cp.async.cg.shared.global [%0], [%1], 16;" :: "r"(dst), "l"(src))
#define CPCOMMIT()     asm volatile("cp.async.commit_group;" ::: "memory")
#define CPWAIT1()      asm volatile("cp.async.wait_group 1;" ::: "memory")

__device__ __forceinline__ void mma_tf32(float* d, const uint32_t* a, const uint32_t* b){
    asm volatile("mma.sync.aligned.m16n8k8.row.col.f32.tf32.tf32.f32 "
        "{%0,%1,%2,%3}, {%4,%5,%6,%7}, {%8,%9}, {%0,%1,%2,%3};"
        : "+f"(d[0]), "+f"(d[1]), "+f"(d[2]), "+f"(d[3])
        : "r"(a[0]), "r"(a[1]), "r"(a[2]), "r"(a[3]), "r"(b[0]), "r"(b[1]));
}

// smem stage layout (bytes)
#define ZPITCH 36
#define AS_RE  0
#define AS_IM  18432
#define BS_RE  36864
#define BS_IM  46080
#define ZSTAGE 55296
#define ZSMEM  (2*ZSTAGE)     // 110592

__global__ void __launch_bounds__(256, 1) zgemm_mma(){
    extern __shared__ char smemc[];
    const uint32_t sb = s2u(smemc);
    const int tid  = threadIdx.x;
    const int lane = tid & 31;
    const int wid  = tid >> 5;
    const int gid  = lane >> 2, tig = lane & 3;
    const int mwarp = wid >> 1;          // 0..3 (rows of 32)
    const int nwarp = wid & 1;           // 0..1 (cols of 32)

    const int slice = blockIdx.y;        // b*33 + k
    const int i0 = (blockIdx.x >> 2) * 128;
    const int n0 = (blockIdx.x & 3) * 64;

    const float* __restrict__ Ar = g_Ar + ((size_t)slice << 16) + (size_t)i0*NMAT;
    const float* __restrict__ Ai = g_Ai + ((size_t)slice << 16) + (size_t)i0*NMAT;
    const float* __restrict__ Br = g_Br + ((size_t)slice << 16) + (size_t)n0*NMAT;
    const float* __restrict__ Bi = g_Bi + ((size_t)slice << 16) + (size_t)n0*NMAT;
    float* __restrict__ Cr = g_Cr + ((size_t)slice << 16);
    float* __restrict__ Ci = g_Ci + ((size_t)slice << 16);

    // accumulators: P1, P2, P3 for 2 m-tiles x 4 n-tiles
    float p1[2][4][4], p2[2][4][4], p3[2][4][4];
#pragma unroll
    for (int mt = 0; mt < 2; mt++)
#pragma unroll
        for (int nt = 0; nt < 4; nt++)
#pragma unroll
            for (int q = 0; q < 4; q++){ p1[mt][nt][q]=0.f; p2[mt][nt][q]=0.f; p3[mt][nt][q]=0.f; }

    // load index mapping (per thread): A: 4 float4/plane, B: 2 float4/plane
    int aRow[4], aK4[4], bRow[2], bK4[2];
#pragma unroll
    for (int h = 0; h < 4; h++){
        int lin = h*256 + tid;
        aRow[h] = lin >> 3; aK4[h] = (lin & 7) * 4;
    }
#pragma unroll
    for (int h = 0; h < 2; h++){
        int lin = h*256 + tid;
        bRow[h] = lin >> 3; bK4[h] = (lin & 7) * 4;
    }

    // issue chunk c into stage st
    auto issue = [&](int c, int st){
        const uint32_t s0 = sb + st*ZSTAGE;
        const int kb = c*32;
#pragma unroll
        for (int h = 0; h < 4; h++){
            uint32_t d = s0 + (uint32_t)((aRow[h]*ZPITCH + aK4[h])*4);
            CP16(d + AS_RE, Ar + (size_t)aRow[h]*NMAT + kb + aK4[h]);
            CP16(d + AS_IM, Ai + (size_t)aRow[h]*NMAT + kb + aK4[h]);
        }
#pragma unroll
        for (int h = 0; h < 2; h++){
            uint32_t d = s0 + (uint32_t)((bRow[h]*ZPITCH + bK4[h])*4);
            CP16(d + BS_RE, Br + (size_t)bRow[h]*NMAT + kb + bK4[h]);
            CP16(d + BS_IM, Bi + (size_t)bRow[h]*NMAT + kb + bK4[h]);
        }
    };

    issue(0, 0); CPCOMMIT();
    issue(1, 1); CPCOMMIT();

    for (int c = 0; c < 8; c++){
        CPWAIT1();
        __syncthreads();
        const int st = c & 1;
        const float* AsRe = (const float*)(smemc + st*ZSTAGE + AS_RE);
        const float* AsIm = (const float*)(smemc + st*ZSTAGE + AS_IM);
        const float* BsRe = (const float*)(smemc + st*ZSTAGE + BS_RE);
        const float* BsIm = (const float*)(smemc + st*ZSTAGE + BS_IM);

#pragma unroll
        for (int kk = 0; kk < 32; kk += 8){
            uint32_t ar[2][4], ai[2][4], as_[2][4];
#pragma unroll
            for (int mt = 0; mt < 2; mt++){
                int r0 = mwarp*32 + mt*16 + gid;
#pragma unroll
                for (int q = 0; q < 4; q++){
                    int rr = r0 + (q & 1)*8;
                    int cc = kk + tig + (q >> 1)*4;
                    float xr = AsRe[rr*ZPITCH + cc];
                    float xi = AsIm[rr*ZPITCH + cc];
                    ar[mt][q]  = __float_as_uint(xr);
                    ai[mt][q]  = __float_as_uint(xi);
                    as_[mt][q] = tf32b(xr + xi);
                }
            }
            uint32_t br[4][2], bi[4][2], bs[4][2];
#pragma unroll
            for (int nt = 0; nt < 4; nt++){
                int n = nwarp*32 + nt*8 + gid;
#pragma unroll
                for (int q = 0; q < 2; q++){
                    int cc = kk + tig + q*4;
                    float xr = BsRe[n*ZPITCH + cc];
                    float xi = BsIm[n*ZPITCH + cc];
                    br[nt][q] = __float_as_uint(xr);
                    bi[nt][q] = __float_as_uint(xi);
                    bs[nt][q] = tf32b(xr + xi);
                }
            }
#pragma unroll
            for (int mt = 0; mt < 2; mt++)
#pragma unroll
                for (int nt = 0; nt < 4; nt++){
                    mma_tf32(p1[mt][nt], ar[mt],  br[nt]);
                    mma_tf32(p2[mt][nt], ai[mt],  bi[nt]);
                    mma_tf32(p3[mt][nt], as_[mt], bs[nt]);
                }
        }
        __syncthreads();
        if (c + 2 < 8) issue(c + 2, st);
        CPCOMMIT();
    }

    // ---- epilogue: combine Gauss terms, stage in smem, coalesced store ----
    float* Csr = (float*)smemc;              // [128][68]
    float* Csi = Csr + 128*68;
#pragma unroll
    for (int mt = 0; mt < 2; mt++){
        int r0 = mwarp*32 + mt*16 + gid;
#pragma unroll
        for (int nt = 0; nt < 4; nt++){
            int col = nwarp*32 + nt*8 + tig*2;
#pragma unroll
            for (int hh = 0; hh < 2; hh++){
                int row = r0 + hh*8;
                float a1 = p1[mt][nt][hh*2+0], a2 = p1[mt][nt][hh*2+1];
                float b1 = p2[mt][nt][hh*2+0], b2 = p2[mt][nt][hh*2+1];
                float c1 = p3[mt][nt][hh*2+0], c2 = p3[mt][nt][hh*2+1];
                float2 vr, vi;
                vr.x = a1 - b1;       vr.y = a2 - b2;
                vi.x = c1 - a1 - b1;  vi.y = c2 - a2 - b2;
                *(float2*)&Csr[row*68 + col] = vr;
                *(float2*)&Csi[row*68 + col] = vi;
            }
        }
    }
    __syncthreads();
#pragma unroll
    for (int h = 0; h < 8; h++){
        int lin = h*256 + tid;
        int row = lin >> 4, c4 = (lin & 15)*4;
        float4 vr = *(const float4*)&Csr[row*68 + c4];
        float4 vi = *(const float4*)&Csi[row*68 + c4];
        *(float4*)(Cr + (size_t)(i0 + row)*NMAT + n0 + c4) = vr;
        *(float4*)(Ci + (size_t)(i0 + row)*NMAT + n0 + c4) = vi;
    }
}

// ---------------- Stage 3: inverse rDFT (smem-staged coalesced stores) ----------------
__global__ void __launch_bounds__(128) idft_kernel(float* __restrict__ out){
    __shared__ float sm[128*67];
    const int tid = threadIdx.x;
    const int T = blockIdx.x*128 + tid;
    const int b = T >> 16;
    const int idx = T & 65535;
    const float* __restrict__ cr = g_Cr + ((size_t)b*NFREQ << 16) + idx;
    const float* __restrict__ ci = g_Ci + ((size_t)b*NFREQ << 16) + idx;
    float R[33], I[33];
#pragma unroll
    for (int k = 0; k < 33; k++){
        R[k] = cr[(size_t)k << 16];
        I[k] = ci[(size_t)k << 16];
    }
    Inv<32>::run(R, I, &sm[tid*67]);
    __syncthreads();
    float4* out4 = (float4*)(out + (size_t)blockIdx.x * 8192);
#pragma unroll
    for (int h = 0; h < 16; h++){
        int l4 = h*128 + tid;
        int tube = l4 >> 4;
        int s4 = l4 & 15;
        const float* p = &sm[tube*67 + s4*4];
        float4 v; v.x = p[0]; v.y = p[1]; v.z = p[2]; v.w = p[3];
        out4[l4] = v;
    }
}

// ---------------- launch ----------------
extern "C" void kernel_launch(void* const* d_in, const int* in_sizes, int n_in,
                              void* d_out, int out_size){
    const float* A = (const float*)d_in[0];
    const float* B = (const float*)d_in[1];
    float* out = (float*)d_out;

    cudaFuncSetAttribute(zgemm_mma, cudaFuncAttributeMaxDynamicSharedMemorySize, ZSMEM);

    dft_fwd_A<<<NTUBE/128, 128>>>(A);
    dft_fwd_B<<<NTUBE/128, 128>>>(B);
    zgemm_mma<<<dim3(8, 8*NFREQ), 256, ZSMEM>>>();
    idft_kernel<<<NTUBE/128, 128>>>(out);
}

// round 12
// speedup vs baseline: 2.3904x; 1.0892x over previous
#include <cuda_runtime.h>
#include <cstdint>
#include <cstddef>

#define NMAT   256
#define NFREQ  33
#define SLICE  (NMAT*NMAT)
#define NTUBE  (8*SLICE)

__device__ float g_Ar[8*NFREQ*SLICE];   // [slice][i*256+j]  (tf32-rounded)
__device__ float g_Ai[8*NFREQ*SLICE];
__device__ float g_Br[8*NFREQ*SLICE];   // [slice][n*256+j]  (tf32-rounded)
__device__ float g_Bi[8*NFREQ*SLICE];
__device__ float g_Cr[8*NFREQ*SLICE];   // [slice][i*256+n]  (fp32)
__device__ float g_Ci[8*NFREQ*SLICE];

// ---------------- compile-time trig ----------------
constexpr double PI_D = 3.14159265358979323846264338327950288;
constexpr double tay_sin(double x){ double t=x,s=x; for(int i=1;i<12;i++){ t*=-(x*x)/double((2*i)*(2*i+1)); s+=t; } return s; }
constexpr double tay_cos(double x){ double t=1,s=1; for(int i=1;i<12;i++){ t*=-(x*x)/double((2*i-1)*(2*i)); s+=t; } return s; }
constexpr double c_cos64(int n){ int m=((n%64)+64)%64; double sg=1; if(m>=32){m-=32;sg=-sg;} if(m>16){m=32-m;sg=-sg;} return sg*tay_cos(PI_D*m/32.0); }
constexpr double c_sin64(int n){ int m=((n%64)+64)%64; double sg=1; if(m>=32){m-=32;sg=-sg;} if(m>16){m=32-m;} return sg*tay_sin(PI_D*m/32.0); }

template<int N> struct CW   { static constexpr float v = (float)c_cos64(N); };
template<int N> struct NSW  { static constexpr float v = (float)(-c_sin64(N)); };
template<int N> struct ICW  { static constexpr float v = (float)(c_cos64(N)/32.0); };
template<int N> struct NISW { static constexpr float v = (float)(-c_sin64(N)/32.0); };

__device__ __forceinline__ float tf32f(float x){
    uint32_t u; asm("cvt.rna.tf32.f32 %0, %1;" : "=r"(u) : "f"(x));
    return __uint_as_float(u);
}
__device__ __forceinline__ uint32_t tf32b(float x){
    uint32_t u; asm("cvt.rna.tf32.f32 %0, %1;" : "=r"(u) : "f"(x));
    return u;
}

// ---------------- forward DFT (radix-2 folded) ----------------
// re[2M]   = sum_{s=0..16} E[s] cos(2pi(2M)s/64)
// re[2M+1] = sum_{s=0..15} F[s] cos(2pi(2M+1)s/64)
// im[2M]   = -sum_{s=1..15} P[s] sin(2pi(2M)s/64)
// im[2M+1] = -sum_{s=1..16} Q[s] sin(2pi(2M+1)s/64)
template<int M,int S> struct F_E {
    static __device__ __forceinline__ float f(const float (&E)[17]){
        return fmaf(E[S], CW<(2*M*S)&63>::v, F_E<M,S-1>::f(E)); }
};
template<int M> struct F_E<M,0> {
    static __device__ __forceinline__ float f(const float (&E)[17]){ return E[0]; }
};
template<int M,int S> struct F_F {
    static __device__ __forceinline__ float f(const float (&F)[16]){
        return fmaf(F[S], CW<((2*M+1)*S)&63>::v, F_F<M,S-1>::f(F)); }
};
template<int M> struct F_F<M,0> {
    static __device__ __forceinline__ float f(const float (&F)[16]){ return F[0]; }
};
template<int M,int S> struct F_P {
    static __device__ __forceinline__ float f(const float (&P)[16]){
        return fmaf(P[S], NSW<(2*M*S)&63>::v, F_P<M,S-1>::f(P)); }
};
template<int M> struct F_P<M,0> {
    static __device__ __forceinline__ float f(const float (&)[16]){ return 0.0f; }
};
template<int M,int S> struct F_Q {
    static __device__ __forceinline__ float f(const float (&Q)[17]){
        return fmaf(Q[S], NSW<((2*M+1)*S)&63>::v, F_Q<M,S-1>::f(Q)); }
};
template<int M> struct F_Q<M,0> {
    static __device__ __forceinline__ float f(const float (&)[17]){ return 0.0f; }
};

template<int M> struct Fwd2 {
    static __device__ __forceinline__ void run(const float (&E)[17], const float (&F)[16],
                                               const float (&P)[16], const float (&Q)[17],
                                               float* __restrict__ pr, float* __restrict__ pi){
        pr[(size_t)(2*M)<<16] = tf32f(F_E<M,16>::f(E));
        pi[(size_t)(2*M)<<16] = tf32f(F_P<M,15>::f(P));
        if constexpr (M < 16){
            pr[(size_t)(2*M+1)<<16] = tf32f(F_F<M,15>::f(F));
            pi[(size_t)(2*M+1)<<16] = tf32f(F_Q<M,16>::f(Q));
        }
        Fwd2<M-1>::run(E, F, P, Q, pr, pi);
    }
};
template<> struct Fwd2<-1> {
    static __device__ __forceinline__ void run(const float (&)[17], const float (&)[16],
                                               const float (&)[16], const float (&)[17],
                                               float*, float*){}
};

__device__ __forceinline__ void fwd_fold_run(const float* __restrict__ a,
                                             float* __restrict__ pr, float* __restrict__ pi){
    float E[17], F[16], P[16], Q[17];
    {
        float a0=a[0], a32=a[32], a16=a[16], a48=a[48];
        E[0]=a0+a32; F[0]=a0-a32; E[16]=a16+a48; Q[16]=a16-a48;
#pragma unroll
        for (int s = 1; s < 16; s++){
            float p1=a[s], p2=a[64-s], p3=a[32-s], p4=a[32+s];
            float eA=p1+p2, eB=p3+p4, oA=p1-p2, oB=p3-p4;
            E[s]=eA+eB; F[s]=eA-eB; P[s]=oA-oB; Q[s]=oA+oB;
        }
    }
    Fwd2<16>::run(E, F, P, Q, pr, pi);
}

// ---------------- inverse DFT (radix-2 folded) ----------------
template<int U,int K> struct I_EC {
    static __device__ __forceinline__ float f(const float (&RP)[16]){
        return fmaf(RP[K], ICW<(2*U*K)&63>::v, I_EC<U,K-1>::f(RP)); }
};
template<int U> struct I_EC<U,0> {
    static __device__ __forceinline__ float f(const float (&)[16]){ return 0.0f; }
};
template<int U,int K> struct I_ES {
    static __device__ __forceinline__ float f(const float (&IM)[16]){
        return fmaf(IM[K], NISW<(2*U*K)&63>::v, I_ES<U,K-1>::f(IM)); }
};
template<int U> struct I_ES<U,0> {
    static __device__ __forceinline__ float f(const float (&)[16]){ return 0.0f; }
};
template<int U,int K> struct I_OC {
    static __device__ __forceinline__ float f(const float (&RM)[16]){
        return fmaf(RM[K], ICW<((2*U+1)*K)&63>::v, I_OC<U,K-1>::f(RM)); }
};
template<int U> struct I_OC<U,0> {
    static __device__ __forceinline__ float f(const float (&)[16]){ return 0.0f; }
};
template<int U,int K> struct I_OS {
    static __device__ __forceinline__ float f(const float (&IP)[16]){
        return fmaf(IP[K], NISW<((2*U+1)*K)&63>::v, I_OS<U,K-1>::f(IP)); }
};
template<int U> struct I_OS<U,0> {
    static __device__ __forceinline__ float f(const float (&)[16]){ return 0.0f; }
};

template<int U> struct Inv2 {
    static __device__ __forceinline__ void run(float R0, float R16, float R32, float I16,
                                               const float (&RP)[16], const float (&RM)[16],
                                               const float (&IP)[16], const float (&IM)[16],
                                               float* __restrict__ sw){
        {
            float Ev = I_EC<U,15>::f(RP);
            Ev = fmaf(R0 + R32, 0.015625f, Ev);
            Ev = fmaf(R16, (U & 1) ? -0.03125f : 0.03125f, Ev);
            float Ov = I_ES<U,15>::f(IM);
            if constexpr (U == 0){
                sw[0] = Ev + Ov;
            } else {
                sw[2*U]      = Ev + Ov;
                sw[64 - 2*U] = Ev - Ov;
            }
        }
        if constexpr (U < 16){
            float Ev = I_OC<U,15>::f(RM);
            Ev = fmaf(R0 - R32, 0.015625f, Ev);
            float Ov = I_OS<U,15>::f(IP);
            Ov = fmaf(I16, (U & 1) ? 0.03125f : -0.03125f, Ov);
            sw[2*U + 1]  = Ev + Ov;
            sw[63 - 2*U] = Ev - Ov;
        }
        Inv2<U-1>::run(R0, R16, R32, I16, RP, RM, IP, IM, sw);
    }
};
template<> struct Inv2<-1> {
    static __device__ __forceinline__ void run(float, float, float, float,
                                               const float (&)[16], const float (&)[16],
                                               const float (&)[16], const float (&)[16],
                                               float*){}
};

// ---------------- Stage 1a: forward rDFT for A ----------------
__global__ void __launch_bounds__(128) dft_fwd_A(const float* __restrict__ in){
    __shared__ float sm[128*67];
    const int tid = threadIdx.x;
    const float4* in4 = (const float4*)(in + (size_t)blockIdx.x * 8192);
#pragma unroll
    for (int h = 0; h < 16; h++){
        int l4 = h*128 + tid;
        float4 v = in4[l4];
        int tube = l4 >> 4;
        int s = (l4 & 15) * 4;
        float* p = &sm[tube*67 + s];
        p[0]=v.x; p[1]=v.y; p[2]=v.z; p[3]=v.w;
    }
    __syncthreads();

    const int T   = blockIdx.x*128 + tid;
    const size_t off = ((size_t)(T >> 16) * NFREQ << 16) + (T & 65535);
    fwd_fold_run(&sm[tid*67], g_Ar + off, g_Ai + off);
}

// ---------------- Stage 1b: forward rDFT for B, transposed write [k][n][j] ----------------
__global__ void __launch_bounds__(128) dft_fwd_B(const float* __restrict__ in){
    __shared__ float sm[128*67];
    const int tid = threadIdx.x;
    const int blk = blockIdx.x;
    const int b   = blk >> 9;
    const int rem = blk & 511;
    const int j0  = (rem >> 6) << 5;
    const int n0  = (rem & 63) << 2;
    const float4* base4 = (const float4*)(in + (size_t)b * SLICE * 64);
#pragma unroll
    for (int h = 0; h < 16; h++){
        int l4 = h*128 + tid;
        int jl  = l4 >> 6;
        int r64 = l4 & 63;
        float4 v = base4[(size_t)((j0 + jl)*NMAT + n0)*16 + r64];
        int tube = (r64 >> 4)*32 + jl;
        int s = (r64 & 15) * 4;
        float* p = &sm[tube*67 + s];
        p[0]=v.x; p[1]=v.y; p[2]=v.z; p[3]=v.w;
    }
    __syncthreads();

    const int jg = j0 + (tid & 31);
    const int ng = n0 + (tid >> 5);
    const size_t off = ((size_t)b * NFREQ << 16) + ng*NMAT + jg;
    fwd_fold_run(&sm[tid*67], g_Br + off, g_Bi + off);
}

// ---------------- Stage 2: mma.sync tf32 Gauss complex GEMM ----------------
__device__ __forceinline__ uint32_t s2u(const void* p){
    uint32_t a;
    asm("{ .reg .u64 t; cvta.to.shared.u64 t, %1; cvt.u32.u64 %0, t; }" : "=r"(a) : "l"(p));
    return a;
}
#define CP16(dst, src) asm volatile("cp.async.cg.shared.global [%0], [%1], 16;" :: "r"(dst), "l"(src))
#define CPCOMMIT()     asm volatile("cp.async.commit_group;" ::: "memory")
#define CPWAIT1()      asm volatile("cp.async.wait_group 1;" ::: "memory")

__device__ __forceinline__ void mma_tf32(float* d, const uint32_t* a, const uint32_t* b){
    asm volatile("mma.sync.aligned.m16n8k8.row.col.f32.tf32.tf32.f32 "
        "{%0,%1,%2,%3}, {%4,%5,%6,%7}, {%8,%9}, {%0,%1,%2,%3};"
        : "+f"(d[0]), "+f"(d[1]), "+f"(d[2]), "+f"(d[3])
        : "r"(a[0]), "r"(a[1]), "r"(a[2]), "r"(a[3]), "r"(b[0]), "r"(b[1]));
}

// smem stage layout (bytes)
#define ZPITCH 36
#define AS_RE  0
#define AS_IM  18432
#define BS_RE  36864
#define BS_IM  46080
#define ZSTAGE 55296
#define ZSMEM  (2*ZSTAGE)     // 110592

__global__ void __launch_bounds__(256, 1) zgemm_mma(){
    extern __shared__ char smemc[];
    const uint32_t sb = s2u(smemc);
    const int tid  = threadIdx.x;
    const int lane = tid & 31;
    const int wid  = tid >> 5;
    const int gid  = lane >> 2, tig = lane & 3;
    const int mwarp = wid >> 1;
    const int nwarp = wid & 1;

    const int slice = blockIdx.y;
    const int i0 = (blockIdx.x >> 2) * 128;
    const int n0 = (blockIdx.x & 3) * 64;

    const float* __restrict__ Ar = g_Ar + ((size_t)slice << 16) + (size_t)i0*NMAT;
    const float* __restrict__ Ai = g_Ai + ((size_t)slice << 16) + (size_t)i0*NMAT;
    const float* __restrict__ Br = g_Br + ((size_t)slice << 16) + (size_t)n0*NMAT;
    const float* __restrict__ Bi = g_Bi + ((size_t)slice << 16) + (size_t)n0*NMAT;
    float* __restrict__ Cr = g_Cr + ((size_t)slice << 16);
    float* __restrict__ Ci = g_Ci + ((size_t)slice << 16);

    float p1[2][4][4], p2[2][4][4], p3[2][4][4];
#pragma unroll
    for (int mt = 0; mt < 2; mt++)
#pragma unroll
        for (int nt = 0; nt < 4; nt++)
#pragma unroll
            for (int q = 0; q < 4; q++){ p1[mt][nt][q]=0.f; p2[mt][nt][q]=0.f; p3[mt][nt][q]=0.f; }

    int aRow[4], aK4[4], bRow[2], bK4[2];
#pragma unroll
    for (int h = 0; h < 4; h++){
        int lin = h*256 + tid;
        aRow[h] = lin >> 3; aK4[h] = (lin & 7) * 4;
    }
#pragma unroll
    for (int h = 0; h < 2; h++){
        int lin = h*256 + tid;
        bRow[h] = lin >> 3; bK4[h] = (lin & 7) * 4;
    }

    auto issue = [&](int c, int st){
        const uint32_t s0 = sb + st*ZSTAGE;
        const int kb = c*32;
#pragma unroll
        for (int h = 0; h < 4; h++){
            uint32_t d = s0 + (uint32_t)((aRow[h]*ZPITCH + aK4[h])*4);
            CP16(d + AS_RE, Ar + (size_t)aRow[h]*NMAT + kb + aK4[h]);
            CP16(d + AS_IM, Ai + (size_t)aRow[h]*NMAT + kb + aK4[h]);
        }
#pragma unroll
        for (int h = 0; h < 2; h++){
            uint32_t d = s0 + (uint32_t)((bRow[h]*ZPITCH + bK4[h])*4);
            CP16(d + BS_RE, Br + (size_t)bRow[h]*NMAT + kb + bK4[h]);
            CP16(d + BS_IM, Bi + (size_t)bRow[h]*NMAT + kb + bK4[h]);
        }
    };

    issue(0, 0); CPCOMMIT();
    issue(1, 1); CPCOMMIT();

    for (int c = 0; c < 8; c++){
        CPWAIT1();
        __syncthreads();
        const int st = c & 1;
        const float* AsRe = (const float*)(smemc + st*ZSTAGE + AS_RE);
        const float* AsIm = (const float*)(smemc + st*ZSTAGE + AS_IM);
        const float* BsRe = (const float*)(smemc + st*ZSTAGE + BS_RE);
        const float* BsIm = (const float*)(smemc + st*ZSTAGE + BS_IM);

#pragma unroll
        for (int kk = 0; kk < 32; kk += 8){
            uint32_t ar[2][4], ai[2][4], as_[2][4];
#pragma unroll
            for (int mt = 0; mt < 2; mt++){
                int r0 = mwarp*32 + mt*16 + gid;
#pragma unroll
                for (int q = 0; q < 4; q++){
                    int rr = r0 + (q & 1)*8;
                    int cc = kk + tig + (q >> 1)*4;
                    float xr = AsRe[rr*ZPITCH + cc];
                    float xi = AsIm[rr*ZPITCH + cc];
                    ar[mt][q]  = __float_as_uint(xr);
                    ai[mt][q]  = __float_as_uint(xi);
                    as_[mt][q] = tf32b(xr + xi);
                }
            }
            uint32_t br[4][2], bi[4][2], bs[4][2];
#pragma unroll
            for (int nt = 0; nt < 4; nt++){
                int n = nwarp*32 + nt*8 + gid;
#pragma unroll
                for (int q = 0; q < 2; q++){
                    int cc = kk + tig + q*4;
                    float xr = BsRe[n*ZPITCH + cc];
                    float xi = BsIm[n*ZPITCH + cc];
                    br[nt][q] = __float_as_uint(xr);
                    bi[nt][q] = __float_as_uint(xi);
                    bs[nt][q] = tf32b(xr + xi);
                }
            }
#pragma unroll
            for (int mt = 0; mt < 2; mt++)
#pragma unroll
                for (int nt = 0; nt < 4; nt++){
                    mma_tf32(p1[mt][nt], ar[mt],  br[nt]);
                    mma_tf32(p2[mt][nt], ai[mt],  bi[nt]);
                    mma_tf32(p3[mt][nt], as_[mt], bs[nt]);
                }
        }
        __syncthreads();
        if (c + 2 < 8) issue(c + 2, st);
        CPCOMMIT();
    }

    // ---- epilogue: combine Gauss terms, stage in smem, coalesced store ----
    float* Csr = (float*)smemc;              // [128][68]
    float* Csi = Csr + 128*68;
#pragma unroll
    for (int mt = 0; mt < 2; mt++){
        int r0 = mwarp*32 + mt*16 + gid;
#pragma unroll
        for (int nt = 0; nt < 4; nt++){
            int col = nwarp*32 + nt*8 + tig*2;
#pragma unroll
            for (int hh = 0; hh < 2; hh++){
                int row = r0 + hh*8;
                float a1 = p1[mt][nt][hh*2+0], a2 = p1[mt][nt][hh*2+1];
                float b1 = p2[mt][nt][hh*2+0], b2 = p2[mt][nt][hh*2+1];
                float c1 = p3[mt][nt][hh*2+0], c2 = p3[mt][nt][hh*2+1];
                float2 vr, vi;
                vr.x = a1 - b1;       vr.y = a2 - b2;
                vi.x = c1 - a1 - b1;  vi.y = c2 - a2 - b2;
                *(float2*)&Csr[row*68 + col] = vr;
                *(float2*)&Csi[row*68 + col] = vi;
            }
        }
    }
    __syncthreads();
#pragma unroll
    for (int h = 0; h < 8; h++){
        int lin = h*256 + tid;
        int row = lin >> 4, c4 = (lin & 15)*4;
        float4 vr = *(const float4*)&Csr[row*68 + c4];
        float4 vi = *(const float4*)&Csi[row*68 + c4];
        *(float4*)(Cr + (size_t)(i0 + row)*NMAT + n0 + c4) = vr;
        *(float4*)(Ci + (size_t)(i0 + row)*NMAT + n0 + c4) = vi;
    }
}

// ---------------- Stage 3: inverse rDFT (folded, smem-staged stores) ----------------
__global__ void __launch_bounds__(128) idft_kernel(float* __restrict__ out){
    __shared__ float sm[128*67];
    const int tid = threadIdx.x;
    const int T = blockIdx.x*128 + tid;
    const int b = T >> 16;
    const int idx = T & 65535;
    const float* __restrict__ cr = g_Cr + ((size_t)b*NFREQ << 16) + idx;
    const float* __restrict__ ci = g_Ci + ((size_t)b*NFREQ << 16) + idx;
    float R[33], I[33];
#pragma unroll
    for (int k = 0; k < 33; k++){
        R[k] = cr[(size_t)k << 16];
        I[k] = ci[(size_t)k << 16];
    }
    float RP[16], RM[16], IP[16], IM[16];
#pragma unroll
    for (int k = 1; k < 16; k++){
        RP[k] = R[k] + R[32-k];  RM[k] = R[k] - R[32-k];
        IP[k] = I[k] + I[32-k];  IM[k] = I[k] - I[32-k];
    }
    Inv2<16>::run(R[0], R[16], R[32], I[16], RP, RM, IP, IM, &sm[tid*67]);
    __syncthreads();
    float4* out4 = (float4*)(out + (size_t)blockIdx.x * 8192);
#pragma unroll
    for (int h = 0; h < 16; h++){
        int l4 = h*128 + tid;
        int tube = l4 >> 4;
        int s4 = l4 & 15;
        const float* p = &sm[tube*67 + s4*4];
        float4 v; v.x = p[0]; v.y = p[1]; v.z = p[2]; v.w = p[3];
        out4[l4] = v;
    }
}

// ---------------- launch ----------------
extern "C" void kernel_launch(void* const* d_in, const int* in_sizes, int n_in,
                              void* d_out, int out_size){
    const float* A = (const float*)d_in[0];
    const float* B = (const float*)d_in[1];
    float* out = (float*)d_out;

    cudaFuncSetAttribute(zgemm_mma, cudaFuncAttributeMaxDynamicSharedMemorySize, ZSMEM);

    dft_fwd_A<<<NTUBE/128, 128>>>(A);
    dft_fwd_B<<<NTUBE/128, 128>>>(B);
    zgemm_mma<<<dim3(8, 8*NFREQ), 256, ZSMEM>>>();
    idft_kernel<<<NTUBE/128, 128>>>(out);
}